// round 1
// baseline (speedup 1.0000x reference)
#include <cuda_runtime.h>
#include <cstdint>

// ============================================================================
// FFTLongConv1D: y[b,l,d] = irfft( rfft(u[b,:,d], 16384) * Hhat[(b*D+d)//B] )[4095+l]
// B=8, L=8192, D=256, K=8192, N=16384.
// Strategy: half-size complex FFT (8192-pt) real-FFT trick, Stockham autosort
// (radix-4 x6 + radix-2) in shared memory, one CTA per (b,d) row.
// ============================================================================

#define NT 512
#define NC 8192            // complex FFT length (N/2)
#define PADB(i) ((i) + ((i) >> 4))   // smem bank padding
#define SBUF 8704          // 8192 + 8192/16 padded float2 slots
#define TWN 2049           // twiddle table entries: e^{-2*pi*i*t/8192}, t=0..2048

#define B_ 8
#define D_ 256
#define L_ 8192

// scratch (allocation-free contract: __device__ globals)
__device__ __align__(16) float2 g_Hhat[D_ * NC];          // 16.8 MB
__device__ __align__(16) float  g_uT[B_ * D_ * L_];       // 64 MB
__device__ __align__(16) float  g_yT[B_ * D_ * L_];       // 64 MB

__device__ __forceinline__ float2 cmul(float2 a, float2 b) {
    return make_float2(fmaf(a.x, b.x, -(a.y * b.y)), fmaf(a.x, b.y, a.y * b.x));
}

__device__ __forceinline__ void build_tw(float2* tw) {
    for (int t = threadIdx.x; t < TWN; t += NT) {
        float sv, cv;
        sincospif(-(float)t * (1.0f / 4096.0f), &sv, &cv);  // -2*pi*t/8192
        tw[t] = make_float2(cv, sv);
    }
}

// One Stockham radix-4 DIF stage. Invariant n*s = 8192, m = n/4, butterflies = 2048.
// i = q + s*p; reads at i + j*2048 (consecutive across lanes -> conflict-free).
__device__ __forceinline__ void radix4_stage(const float2* __restrict__ src,
                                             float2* __restrict__ dst,
                                             const float2* __restrict__ tw,
                                             int sLog) {
    const int s = 1 << sLog;
#pragma unroll
    for (int t = 0; t < 4; t++) {
        int i = threadIdx.x + t * NT;             // 0..2047
        float2 a = src[PADB(i)];
        float2 b = src[PADB(i + 2048)];
        float2 c = src[PADB(i + 4096)];
        float2 d = src[PADB(i + 6144)];
        int twi = i & ~(s - 1);                   // p*s  (< 2048)
        float2 w1 = tw[twi];
        float2 w2 = cmul(w1, w1);
        float2 w3 = cmul(w2, w1);
        float2 apc = make_float2(a.x + c.x, a.y + c.y);
        float2 amc = make_float2(a.x - c.x, a.y - c.y);
        float2 bpd = make_float2(b.x + d.x, b.y + d.y);
        float2 bmd = make_float2(b.x - d.x, b.y - d.y);
        float2 mjb = make_float2(bmd.y, -bmd.x);  // -i * (b - d)
        float2 y0 = make_float2(apc.x + bpd.x, apc.y + bpd.y);
        float2 y1 = cmul(w1, make_float2(amc.x + mjb.x, amc.y + mjb.y));
        float2 y2 = cmul(w2, make_float2(apc.x - bpd.x, apc.y - bpd.y));
        float2 y3 = cmul(w3, make_float2(amc.x - mjb.x, amc.y - mjb.y));
        int base = (i & (s - 1)) + ((i >> sLog) << (sLog + 2));  // q + 4*s*p
        dst[PADB(base)]         = y0;
        dst[PADB(base + s)]     = y1;
        dst[PADB(base + 2 * s)] = y2;
        dst[PADB(base + 3 * s)] = y3;
    }
}

// Final radix-2 stage (n=2, s=4096, twiddle = 1). Fully consecutive accesses.
__device__ __forceinline__ void radix2_final(const float2* __restrict__ src,
                                             float2* __restrict__ dst) {
#pragma unroll
    for (int t = 0; t < 8; t++) {
        int i = threadIdx.x + t * NT;             // 0..4095
        float2 a = src[PADB(i)];
        float2 b = src[PADB(i + 4096)];
        dst[PADB(i)]        = make_float2(a.x + b.x, a.y + b.y);
        dst[PADB(i + 4096)] = make_float2(a.x - b.x, a.y - b.y);
    }
}

// 8192-pt forward complex FFT, natural order in -> natural order out.
// Input must be in bufA; returns pointer holding result (== bufB).
__device__ __forceinline__ float2* fft8192(float2* bufA, float2* bufB,
                                           const float2* tw) {
    float2 *src = bufA, *dst = bufB;
#pragma unroll
    for (int st = 0; st < 6; st++) {
        radix4_stage(src, dst, tw, 2 * st);       // s = 1,4,16,64,256,1024
        __syncthreads();
        float2* tmp = src; src = dst; dst = tmp;
    }
    radix2_final(src, dst);                       // s = 4096
    __syncthreads();
    return dst;
}

// ============================================================================
// Filter spectra: Hhat[f][k] = rfft(h[f] zero-padded to 16384)[k], k=0..8191,
// Nyquist (k=8192) packed into imag of bin 0.
// ============================================================================
__global__ void __launch_bounds__(NT) hfft_kernel(const float* __restrict__ h) {
    extern __shared__ float2 sm[];
    float2* bufA = sm;
    float2* bufB = sm + SBUF;
    float2* tw   = sm + 2 * SBUF;
    int dIdx = blockIdx.x;
    const float2* hrow = (const float2*)(h + (size_t)dIdx * 8192);
    for (int i = threadIdx.x; i < 4096; i += NT) bufA[PADB(i)] = hrow[i];
    for (int i = 4096 + threadIdx.x; i < 8192; i += NT) bufA[PADB(i)] = make_float2(0.f, 0.f);
    build_tw(tw);
    __syncthreads();
    float2* Z = fft8192(bufA, bufB, tw);
    float2* out = g_Hhat + (size_t)dIdx * NC;
    float2 chalf; { float sv, cv; sincospif(-1.0f / 8192.0f, &sv, &cv); chalf = make_float2(cv, sv); }
    for (int k = threadIdx.x; k <= 4096; k += NT) {
        if (k == 0) {
            float2 Z0 = Z[PADB(0)];
            out[0] = make_float2(Z0.x + Z0.y, Z0.x - Z0.y);   // (X[0], X[Nyq])
        } else {
            int k2 = 8192 - k;
            float2 Zk  = Z[PADB(k)];
            float2 Zk2 = Z[PADB(k2)];
            float2 E  = make_float2(0.5f * (Zk.x + Zk2.x), 0.5f * (Zk.y - Zk2.y));
            float2 Dv = make_float2(Zk.x - Zk2.x, Zk.y + Zk2.y);
            float2 O  = make_float2(0.5f * Dv.y, -0.5f * Dv.x);  // (Z-conj)*(-i)/2
            float2 Wk = tw[k >> 1];                               // e^{-2pi i k/16384}
            if (k & 1) Wk = cmul(Wk, chalf);
            float2 WO = cmul(Wk, O);
            out[k] = make_float2(E.x + WO.x, E.y + WO.y);         // X[k]=E+Wk*O
            if (k < 4096)
                out[k2] = make_float2(E.x - WO.x, -(E.y - WO.y)); // X[Nc-k]=conj(E-Wk*O)
        }
    }
}

// ============================================================================
// Transposes: (B, L, D) <-> row-contiguous (B*D, L)
// ============================================================================
__global__ void transpose_in(const float* __restrict__ u) {
    __shared__ float tile[32][33];
    int b  = blockIdx.z;
    int d0 = blockIdx.x * 32;
    int l0 = blockIdx.y * 32;
    const float* ub = u + (size_t)b * L_ * D_;
#pragma unroll
    for (int j = 0; j < 4; j++) {
        int l = l0 + threadIdx.y + j * 8;
        tile[threadIdx.y + j * 8][threadIdx.x] = ub[(size_t)l * D_ + d0 + threadIdx.x];
    }
    __syncthreads();
    float* ob = g_uT + (size_t)b * D_ * L_;
#pragma unroll
    for (int j = 0; j < 4; j++) {
        int dd = d0 + threadIdx.y + j * 8;
        ob[(size_t)dd * L_ + l0 + threadIdx.x] = tile[threadIdx.x][threadIdx.y + j * 8];
    }
}

__global__ void transpose_out(float* __restrict__ y) {
    __shared__ float tile[32][33];
    int b  = blockIdx.z;
    int d0 = blockIdx.x * 32;
    int l0 = blockIdx.y * 32;
    const float* ib = g_yT + (size_t)b * D_ * L_;
#pragma unroll
    for (int j = 0; j < 4; j++) {
        int dd = d0 + threadIdx.y + j * 8;
        tile[threadIdx.y + j * 8][threadIdx.x] = ib[(size_t)dd * L_ + l0 + threadIdx.x];
    }
    __syncthreads();
    float* yb = y + (size_t)b * L_ * D_;
#pragma unroll
    for (int j = 0; j < 4; j++) {
        int l = l0 + threadIdx.y + j * 8;
        yb[(size_t)l * D_ + d0 + threadIdx.x] = tile[threadIdx.x][threadIdx.y + j * 8];
    }
}

// ============================================================================
// Per-row conv: forward FFT, fused spectral (rfft combine * Hhat, irfft pack
// with conjugation folded), inverse FFT via conj trick, extract + store.
// ============================================================================
__global__ void __launch_bounds__(NT) conv_kernel() {
    extern __shared__ float2 sm[];
    float2* bufA = sm;
    float2* bufB = sm + SBUF;
    float2* tw   = sm + 2 * SBUF;
    int r = blockIdx.x;              // r = b*256 + d
    int f = r >> 3;                  // filter index = (b*D + d) // B  (B=8)

    const float2* urow = (const float2*)(g_uT + (size_t)r * L_);
    for (int i = threadIdx.x; i < 4096; i += NT) bufA[PADB(i)] = urow[i];
    for (int i = 4096 + threadIdx.x; i < 8192; i += NT) bufA[PADB(i)] = make_float2(0.f, 0.f);
    build_tw(tw);
    __syncthreads();

    float2* Z  = fft8192(bufA, bufB, tw);   // Z in bufB
    float2* Zc = bufA;                       // conj(packed spectrum) -> bufA
    const float2* Hrow = g_Hhat + (size_t)f * NC;
    float2 chalf; { float sv, cv; sincospif(-1.0f / 8192.0f, &sv, &cv); chalf = make_float2(cv, sv); }

    for (int k = threadIdx.x; k <= 4096; k += NT) {
        if (k == 0) {
            float2 Z0 = Z[PADB(0)];
            float X0 = Z0.x + Z0.y;          // X[0]
            float XN = Z0.x - Z0.y;          // X[Nyquist]
            float2 H0 = Hrow[0];             // (H[0], H[Nyq]) both real
            float Y0 = X0 * H0.x;
            float YN = XN * H0.y;
            Zc[PADB(0)] = make_float2(0.5f * (Y0 + YN), -0.5f * (Y0 - YN));
        } else {
            int k2 = 8192 - k;
            float2 Zk  = Z[PADB(k)];
            float2 Zk2 = Z[PADB(k2)];
            // forward rfft combine
            float2 E  = make_float2(0.5f * (Zk.x + Zk2.x), 0.5f * (Zk.y - Zk2.y));
            float2 Dv = make_float2(Zk.x - Zk2.x, Zk.y + Zk2.y);
            float2 O  = make_float2(0.5f * Dv.y, -0.5f * Dv.x);
            float2 Wk = tw[k >> 1];
            if (k & 1) Wk = cmul(Wk, chalf);
            float2 WO  = cmul(Wk, O);
            float2 Xk  = make_float2(E.x + WO.x, E.y + WO.y);
            float2 Xk2 = make_float2(E.x - WO.x, -(E.y - WO.y));
            // spectral multiply
            float2 Yk  = cmul(Xk,  Hrow[k]);
            float2 Yk2 = cmul(Xk2, Hrow[k2]);
            // irfft pre-pack: E' = (Y[k]+conj(Y[k2]))/2, O' = conj(Wk)*(Y[k]-conj(Y[k2]))/2
            float2 Ep = make_float2(0.5f * (Yk.x + Yk2.x), 0.5f * (Yk.y - Yk2.y));
            float2 Dy = make_float2(0.5f * (Yk.x - Yk2.x), 0.5f * (Yk.y + Yk2.y));
            float2 Op = make_float2(fmaf(Wk.x, Dy.x,  Wk.y * Dy.y),
                                    fmaf(Wk.x, Dy.y, -(Wk.y * Dy.x)));
            // store conj(Zi): Zc[k] = conj(E'+iO'), Zc[k2] = E'-iO'
            Zc[PADB(k)] = make_float2(Ep.x - Op.y, -(Ep.y + Op.x));
            if (k < 4096)
                Zc[PADB(k2)] = make_float2(Ep.x + Op.y, Ep.y - Op.x);
        }
    }
    __syncthreads();

    float2* R = fft8192(bufA, bufB, tw);     // fft(conj(Zi)); z[n] = conj(R[n])/8192
    float* yrow = g_yT + (size_t)r * L_;
    const float invN = 1.0f / 8192.0f;
    for (int l = threadIdx.x; l < L_; l += NT) {
        int tpos = 4095 + l;                 // y_full[start + l]
        float2 zr = R[PADB(tpos >> 1)];
        yrow[l] = (tpos & 1) ? (-zr.y * invN) : (zr.x * invN);
    }
}

// ============================================================================
extern "C" void kernel_launch(void* const* d_in, const int* in_sizes, int n_in,
                              void* d_out, int out_size) {
    const float* u = (const float*)d_in[0];   // (8, 8192, 256)
    const float* h = (const float*)d_in[1];   // (256, 8192)
    float* out = (float*)d_out;               // (8, 8192, 256)

    size_t smem = (size_t)(2 * SBUF + TWN) * sizeof(float2);  // ~152 KB
    cudaFuncSetAttribute(hfft_kernel, cudaFuncAttributeMaxDynamicSharedMemorySize, (int)smem);
    cudaFuncSetAttribute(conv_kernel, cudaFuncAttributeMaxDynamicSharedMemorySize, (int)smem);

    dim3 tb(32, 8);
    hfft_kernel<<<D_, NT, smem>>>(h);
    transpose_in<<<dim3(D_ / 32, L_ / 32, B_), tb>>>(u);
    conv_kernel<<<B_ * D_, NT, smem>>>();
    transpose_out<<<dim3(D_ / 32, L_ / 32, B_), tb>>>(out);
    (void)in_sizes; (void)n_in; (void)out_size;
}

// round 2
// speedup vs baseline: 1.4390x; 1.4390x over previous
#include <cuda_runtime.h>
#include <cstdint>

// ============================================================================
// FFTLongConv1D: y[b,l,d] = irfft( rfft(u[b,:,d], 16384) * Hhat[(b*D+d)//B] )[4095+l]
// B=8, L=8192, D=256, K=8192, N=16384.
// Half-size complex FFT (8192-pt) real-FFT trick; Stockham autosort
// radix-8 x4 + radix-2 in shared memory; 1024 threads, one CTA per (b,d) row.
// ============================================================================

#define NT 1024
#define NC 8192            // complex FFT length (N/2)
#define PADB(i) ((i) + ((i) >> 4))   // smem bank padding
#define SBUF 8704          // 8192 + 8192/16 padded float2 slots
#define TWN 2049           // twiddle table: e^{-2*pi*i*t/8192}, t=0..2048

#define B_ 8
#define D_ 256
#define L_ 8192

// scratch (allocation-free contract: __device__ globals)
__device__ __align__(16) float2 g_Hhat[D_ * NC];          // 16.8 MB
__device__ __align__(16) float  g_uT[B_ * D_ * L_];       // 64 MB
__device__ __align__(16) float  g_yT[B_ * D_ * L_];       // 64 MB

__device__ __forceinline__ float2 cmul(float2 a, float2 b) {
    return make_float2(fmaf(a.x, b.x, -(a.y * b.y)), fmaf(a.x, b.y, a.y * b.x));
}
__device__ __forceinline__ float2 cadd(float2 a, float2 b) { return make_float2(a.x + b.x, a.y + b.y); }
__device__ __forceinline__ float2 csub(float2 a, float2 b) { return make_float2(a.x - b.x, a.y - b.y); }

__device__ __forceinline__ void build_tw(float2* tw) {
    for (int t = threadIdx.x; t < TWN; t += NT) {
        float sv, cv;
        sincospif(-(float)t * (1.0f / 4096.0f), &sv, &cv);  // -2*pi*t/8192
        tw[t] = make_float2(cv, sv);
    }
}

// One Stockham radix-8 DIF stage. N=8192, butterflies = 1024 (one per thread).
// i = q + s*p; reads at i + m*1024 (consecutive across lanes -> conflict-free).
__device__ __forceinline__ void radix8_stage(const float2* __restrict__ src,
                                             float2* __restrict__ dst,
                                             const float2* __restrict__ tw,
                                             int sLog) {
    const int s = 1 << sLog;
    const int i = threadIdx.x;                    // 0..1023
    float2 x0 = src[PADB(i)];
    float2 x1 = src[PADB(i + 1024)];
    float2 x2 = src[PADB(i + 2048)];
    float2 x3 = src[PADB(i + 3072)];
    float2 x4 = src[PADB(i + 4096)];
    float2 x5 = src[PADB(i + 5120)];
    float2 x6 = src[PADB(i + 6144)];
    float2 x7 = src[PADB(i + 7168)];

    // DFT8: even/odd split into two DFT4s, combine with w8 factors.
    float2 t0 = cadd(x0, x4), t1 = csub(x0, x4);
    float2 t2 = cadd(x2, x6), t3 = csub(x2, x6);
    float2 t3m = make_float2(t3.y, -t3.x);        // -i*t3
    float2 E0 = cadd(t0, t2), E2 = csub(t0, t2);
    float2 E1 = cadd(t1, t3m), E3 = csub(t1, t3m);

    float2 u0 = cadd(x1, x5), u1 = csub(x1, x5);
    float2 u2 = cadd(x3, x7), u3 = csub(x3, x7);
    float2 u3m = make_float2(u3.y, -u3.x);
    float2 O0 = cadd(u0, u2), O2 = csub(u0, u2);
    float2 O1 = cadd(u1, u3m), O3 = csub(u1, u3m);

    const float c = 0.70710678118654752f;
    float2 wO1 = make_float2(c * (O1.x + O1.y), c * (O1.y - O1.x));   // w8^1*O1
    float2 wO2 = make_float2(O2.y, -O2.x);                            // -i*O2
    float2 wO3 = make_float2(c * (O3.y - O3.x), -c * (O3.x + O3.y));  // w8^3*O3

    float2 X0 = cadd(E0, O0),  X4 = csub(E0, O0);
    float2 X1 = cadd(E1, wO1), X5 = csub(E1, wO1);
    float2 X2 = cadd(E2, wO2), X6 = csub(E2, wO2);
    float2 X3 = cadd(E3, wO3), X7 = csub(E3, wO3);

    // Outer twiddles: w1 = e^{-2pi i * p*s / 8192}, y_j = w1^j * X_j.
    const int ps = i & ~(s - 1);                  // p*s  (<= 1023)
    float2 w1 = tw[ps];
    float2 w2 = cmul(w1, w1);
    float2 w3 = cmul(w2, w1);
    float2 w4 = cmul(w2, w2);
    float2 w5 = cmul(w2, w3);
    float2 w6 = cmul(w3, w3);
    float2 w7 = cmul(w3, w4);

    const int base = (i & (s - 1)) + ((i >> sLog) << (sLog + 3));  // q + 8*s*p
    dst[PADB(base)]         = X0;
    dst[PADB(base + s)]     = cmul(w1, X1);
    dst[PADB(base + 2 * s)] = cmul(w2, X2);
    dst[PADB(base + 3 * s)] = cmul(w3, X3);
    dst[PADB(base + 4 * s)] = cmul(w4, X4);
    dst[PADB(base + 5 * s)] = cmul(w5, X5);
    dst[PADB(base + 6 * s)] = cmul(w6, X6);
    dst[PADB(base + 7 * s)] = cmul(w7, X7);
}

// Final radix-2 stage (s=4096, twiddle = 1). Fully consecutive accesses.
__device__ __forceinline__ void radix2_final(const float2* __restrict__ src,
                                             float2* __restrict__ dst) {
#pragma unroll
    for (int t = 0; t < 4; t++) {
        int i = threadIdx.x + t * NT;             // 0..4095
        float2 a = src[PADB(i)];
        float2 b = src[PADB(i + 4096)];
        dst[PADB(i)]        = cadd(a, b);
        dst[PADB(i + 4096)] = csub(a, b);
    }
}

// 8192-pt forward complex FFT, natural order in -> natural order out.
// Input in bufA; result lands in bufB.
__device__ __forceinline__ float2* fft8192(float2* bufA, float2* bufB,
                                           const float2* tw) {
    float2 *src = bufA, *dst = bufB;
#pragma unroll
    for (int st = 0; st < 4; st++) {
        radix8_stage(src, dst, tw, 3 * st);       // s = 1, 8, 64, 512
        __syncthreads();
        float2* tmp = src; src = dst; dst = tmp;
    }
    radix2_final(src, dst);                       // s = 4096
    __syncthreads();
    return dst;
}

// ============================================================================
// Filter spectra: Hhat[f][k] = rfft(h[f] zero-padded to 16384)[k], k=0..8191,
// Nyquist (k=8192) packed into imag of bin 0.
// ============================================================================
__global__ void __launch_bounds__(NT) hfft_kernel(const float* __restrict__ h) {
    extern __shared__ float2 sm[];
    float2* bufA = sm;
    float2* bufB = sm + SBUF;
    float2* tw   = sm + 2 * SBUF;
    int dIdx = blockIdx.x;
    const float2* hrow = (const float2*)(h + (size_t)dIdx * 8192);
    for (int i = threadIdx.x; i < 4096; i += NT) bufA[PADB(i)] = hrow[i];
    for (int i = 4096 + threadIdx.x; i < 8192; i += NT) bufA[PADB(i)] = make_float2(0.f, 0.f);
    build_tw(tw);
    __syncthreads();
    float2* Z = fft8192(bufA, bufB, tw);
    float2* out = g_Hhat + (size_t)dIdx * NC;
    float2 chalf; { float sv, cv; sincospif(-1.0f / 8192.0f, &sv, &cv); chalf = make_float2(cv, sv); }
    for (int k = threadIdx.x; k <= 4096; k += NT) {
        if (k == 0) {
            float2 Z0 = Z[PADB(0)];
            out[0] = make_float2(Z0.x + Z0.y, Z0.x - Z0.y);   // (X[0], X[Nyq])
        } else {
            int k2 = 8192 - k;
            float2 Zk  = Z[PADB(k)];
            float2 Zk2 = Z[PADB(k2)];
            float2 E  = make_float2(0.5f * (Zk.x + Zk2.x), 0.5f * (Zk.y - Zk2.y));
            float2 Dv = make_float2(Zk.x - Zk2.x, Zk.y + Zk2.y);
            float2 O  = make_float2(0.5f * Dv.y, -0.5f * Dv.x);  // (Z-conj)*(-i)/2
            float2 Wk = tw[k >> 1];                               // e^{-2pi i k/16384}
            if (k & 1) Wk = cmul(Wk, chalf);
            float2 WO = cmul(Wk, O);
            out[k] = make_float2(E.x + WO.x, E.y + WO.y);         // X[k]=E+Wk*O
            if (k < 4096)
                out[k2] = make_float2(E.x - WO.x, -(E.y - WO.y)); // X[Nc-k]=conj(E-Wk*O)
        }
    }
}

// ============================================================================
// Transposes: (B, L, D) <-> row-contiguous (B*D, L)
// ============================================================================
__global__ void transpose_in(const float* __restrict__ u) {
    __shared__ float tile[32][33];
    int b  = blockIdx.z;
    int d0 = blockIdx.x * 32;
    int l0 = blockIdx.y * 32;
    const float* ub = u + (size_t)b * L_ * D_;
#pragma unroll
    for (int j = 0; j < 4; j++) {
        int l = l0 + threadIdx.y + j * 8;
        tile[threadIdx.y + j * 8][threadIdx.x] = ub[(size_t)l * D_ + d0 + threadIdx.x];
    }
    __syncthreads();
    float* ob = g_uT + (size_t)b * D_ * L_;
#pragma unroll
    for (int j = 0; j < 4; j++) {
        int dd = d0 + threadIdx.y + j * 8;
        ob[(size_t)dd * L_ + l0 + threadIdx.x] = tile[threadIdx.x][threadIdx.y + j * 8];
    }
}

__global__ void transpose_out(float* __restrict__ y) {
    __shared__ float tile[32][33];
    int b  = blockIdx.z;
    int d0 = blockIdx.x * 32;
    int l0 = blockIdx.y * 32;
    const float* ib = g_yT + (size_t)b * D_ * L_;
#pragma unroll
    for (int j = 0; j < 4; j++) {
        int dd = d0 + threadIdx.y + j * 8;
        tile[threadIdx.y + j * 8][threadIdx.x] = ib[(size_t)dd * L_ + l0 + threadIdx.x];
    }
    __syncthreads();
    float* yb = y + (size_t)b * L_ * D_;
#pragma unroll
    for (int j = 0; j < 4; j++) {
        int l = l0 + threadIdx.y + j * 8;
        yb[(size_t)l * D_ + d0 + threadIdx.x] = tile[threadIdx.x][threadIdx.y + j * 8];
    }
}

// ============================================================================
// Per-row conv: forward FFT, fused spectral (rfft combine * Hhat, irfft pack
// with conjugation folded), inverse FFT via conj trick, extract + store.
// ============================================================================
__global__ void __launch_bounds__(NT) conv_kernel() {
    extern __shared__ float2 sm[];
    float2* bufA = sm;
    float2* bufB = sm + SBUF;
    float2* tw   = sm + 2 * SBUF;
    int r = blockIdx.x;              // r = b*256 + d
    int f = r >> 3;                  // filter index = (b*D + d) // B  (B=8)

    const float2* urow = (const float2*)(g_uT + (size_t)r * L_);
    for (int i = threadIdx.x; i < 4096; i += NT) bufA[PADB(i)] = urow[i];
    for (int i = 4096 + threadIdx.x; i < 8192; i += NT) bufA[PADB(i)] = make_float2(0.f, 0.f);
    build_tw(tw);
    __syncthreads();

    float2* Z  = fft8192(bufA, bufB, tw);   // Z in bufB
    float2* Zc = bufA;                       // conj(packed spectrum) -> bufA
    const float2* Hrow = g_Hhat + (size_t)f * NC;
    float2 chalf; { float sv, cv; sincospif(-1.0f / 8192.0f, &sv, &cv); chalf = make_float2(cv, sv); }

    for (int k = threadIdx.x; k <= 4096; k += NT) {
        if (k == 0) {
            float2 Z0 = Z[PADB(0)];
            float X0 = Z0.x + Z0.y;          // X[0]
            float XN = Z0.x - Z0.y;          // X[Nyquist]
            float2 H0 = Hrow[0];             // (H[0], H[Nyq]) both real
            float Y0 = X0 * H0.x;
            float YN = XN * H0.y;
            Zc[PADB(0)] = make_float2(0.5f * (Y0 + YN), -0.5f * (Y0 - YN));
        } else {
            int k2 = 8192 - k;
            float2 Zk  = Z[PADB(k)];
            float2 Zk2 = Z[PADB(k2)];
            // forward rfft combine
            float2 E  = make_float2(0.5f * (Zk.x + Zk2.x), 0.5f * (Zk.y - Zk2.y));
            float2 Dv = make_float2(Zk.x - Zk2.x, Zk.y + Zk2.y);
            float2 O  = make_float2(0.5f * Dv.y, -0.5f * Dv.x);
            float2 Wk = tw[k >> 1];
            if (k & 1) Wk = cmul(Wk, chalf);
            float2 WO  = cmul(Wk, O);
            float2 Xk  = make_float2(E.x + WO.x, E.y + WO.y);
            float2 Xk2 = make_float2(E.x - WO.x, -(E.y - WO.y));
            // spectral multiply
            float2 Yk  = cmul(Xk,  Hrow[k]);
            float2 Yk2 = cmul(Xk2, Hrow[k2]);
            // irfft pre-pack: E' = (Y[k]+conj(Y[k2]))/2, O' = conj(Wk)*(Y[k]-conj(Y[k2]))/2
            float2 Ep = make_float2(0.5f * (Yk.x + Yk2.x), 0.5f * (Yk.y - Yk2.y));
            float2 Dy = make_float2(0.5f * (Yk.x - Yk2.x), 0.5f * (Yk.y + Yk2.y));
            float2 Op = make_float2(fmaf(Wk.x, Dy.x,  Wk.y * Dy.y),
                                    fmaf(Wk.x, Dy.y, -(Wk.y * Dy.x)));
            // store conj(Zi): Zc[k] = conj(E'+iO'), Zc[k2] = E'-iO'
            Zc[PADB(k)] = make_float2(Ep.x - Op.y, -(Ep.y + Op.x));
            if (k < 4096)
                Zc[PADB(k2)] = make_float2(Ep.x + Op.y, Ep.y - Op.x);
        }
    }
    __syncthreads();

    float2* R = fft8192(bufA, bufB, tw);     // fft(conj(Zi)); z[n] = conj(R[n])/8192
    float* yrow = g_yT + (size_t)r * L_;
    const float invN = 1.0f / 8192.0f;
    for (int l = threadIdx.x; l < L_; l += NT) {
        int tpos = 4095 + l;                 // y_full[start + l]
        float2 zr = R[PADB(tpos >> 1)];
        yrow[l] = (tpos & 1) ? (-zr.y * invN) : (zr.x * invN);
    }
}

// ============================================================================
extern "C" void kernel_launch(void* const* d_in, const int* in_sizes, int n_in,
                              void* d_out, int out_size) {
    const float* u = (const float*)d_in[0];   // (8, 8192, 256)
    const float* h = (const float*)d_in[1];   // (256, 8192)
    float* out = (float*)d_out;               // (8, 8192, 256)

    size_t smem = (size_t)(2 * SBUF + TWN) * sizeof(float2);  // ~152 KB
    cudaFuncSetAttribute(hfft_kernel, cudaFuncAttributeMaxDynamicSharedMemorySize, (int)smem);
    cudaFuncSetAttribute(conv_kernel, cudaFuncAttributeMaxDynamicSharedMemorySize, (int)smem);

    dim3 tb(32, 8);
    hfft_kernel<<<D_, NT, smem>>>(h);
    transpose_in<<<dim3(D_ / 32, L_ / 32, B_), tb>>>(u);
    conv_kernel<<<B_ * D_, NT, smem>>>();
    transpose_out<<<dim3(D_ / 32, L_ / 32, B_), tb>>>(out);
    (void)in_sizes; (void)n_in; (void)out_size;
}

// round 3
// speedup vs baseline: 1.5754x; 1.0948x over previous
#include <cuda_runtime.h>
#include <cstdint>

// ============================================================================
// FFTLongConv1D: y[b,l,d] = irfft( rfft(u[b,:,d], 16384) * Hhat[(b*D+d)//B] )[4095+l]
// B=8, L=8192, D=256, K=8192, N=16384.
// Half-size complex FFT (8192-pt) real-FFT trick; IN-PLACE Stockham radix-8 x4
// + radix-2; NT=512 threads, 2 CTAs/SM (86 KB smem each).
// ============================================================================

#define NT 512
#define NC 8192            // complex FFT length (N/2)
#define PADB(i) ((i) + ((i) >> 4))   // smem bank padding
#define SBUF 8704          // 8192 + 8192/16 padded float2 slots
#define TWN 2049           // twiddle table: e^{-2*pi*i*t/8192}, t=0..2048

#define B_ 8
#define D_ 256
#define L_ 8192

__device__ __align__(16) float2 g_Hhat[D_ * NC];          // 16.8 MB
__device__ __align__(16) float  g_uT[B_ * D_ * L_];       // 64 MB
__device__ __align__(16) float  g_yT[B_ * D_ * L_];       // 64 MB

__device__ __forceinline__ float2 cmul(float2 a, float2 b) {
    return make_float2(fmaf(a.x, b.x, -(a.y * b.y)), fmaf(a.x, b.y, a.y * b.x));
}
__device__ __forceinline__ float2 cadd(float2 a, float2 b) { return make_float2(a.x + b.x, a.y + b.y); }
__device__ __forceinline__ float2 csub(float2 a, float2 b) { return make_float2(a.x - b.x, a.y - b.y); }

__device__ __forceinline__ void build_tw(float2* tw) {
    for (int t = threadIdx.x; t < TWN; t += NT) {
        float sv, cv;
        sincospif(-(float)t * (1.0f / 4096.0f), &sv, &cv);  // -2*pi*t/8192
        tw[t] = make_float2(cv, sv);
    }
}

// Compute one radix-8 DIF butterfly (8 inputs in x[]) and write results.
__device__ __forceinline__ void bf8_compute_store(float2* __restrict__ buf,
                                                  const float2* __restrict__ tw,
                                                  float2 x0, float2 x1, float2 x2, float2 x3,
                                                  float2 x4, float2 x5, float2 x6, float2 x7,
                                                  int i, int sLog) {
    const int s = 1 << sLog;
    float2 t0 = cadd(x0, x4), t1 = csub(x0, x4);
    float2 t2 = cadd(x2, x6), t3 = csub(x2, x6);
    float2 t3m = make_float2(t3.y, -t3.x);        // -i*t3
    float2 E0 = cadd(t0, t2), E2 = csub(t0, t2);
    float2 E1 = cadd(t1, t3m), E3 = csub(t1, t3m);

    float2 u0 = cadd(x1, x5), u1 = csub(x1, x5);
    float2 u2 = cadd(x3, x7), u3 = csub(x3, x7);
    float2 u3m = make_float2(u3.y, -u3.x);
    float2 O0 = cadd(u0, u2), O2 = csub(u0, u2);
    float2 O1 = cadd(u1, u3m), O3 = csub(u1, u3m);

    const float c = 0.70710678118654752f;
    float2 wO1 = make_float2(c * (O1.x + O1.y), c * (O1.y - O1.x));   // w8^1*O1
    float2 wO2 = make_float2(O2.y, -O2.x);                            // -i*O2
    float2 wO3 = make_float2(c * (O3.y - O3.x), -c * (O3.x + O3.y));  // w8^3*O3

    float2 X0 = cadd(E0, O0),  X4 = csub(E0, O0);
    float2 X1 = cadd(E1, wO1), X5 = csub(E1, wO1);
    float2 X2 = cadd(E2, wO2), X6 = csub(E2, wO2);
    float2 X3 = cadd(E3, wO3), X7 = csub(E3, wO3);

    const int ps = i & ~(s - 1);                  // p*s (<=1023)
    float2 w1 = tw[ps];
    float2 w2 = cmul(w1, w1);
    float2 w3 = cmul(w2, w1);
    float2 w4 = cmul(w2, w2);
    float2 w5 = cmul(w2, w3);
    float2 w6 = cmul(w3, w3);
    float2 w7 = cmul(w3, w4);

    const int base = (i & (s - 1)) + ((i >> sLog) << (sLog + 3));  // q + 8*s*p
    buf[PADB(base)]         = X0;
    buf[PADB(base + s)]     = cmul(w1, X1);
    buf[PADB(base + 2 * s)] = cmul(w2, X2);
    buf[PADB(base + 3 * s)] = cmul(w3, X3);
    buf[PADB(base + 4 * s)] = cmul(w4, X4);
    buf[PADB(base + 5 * s)] = cmul(w5, X5);
    buf[PADB(base + 6 * s)] = cmul(w6, X6);
    buf[PADB(base + 7 * s)] = cmul(w7, X7);
}

// In-place radix-8 stage: NT=512 threads x 2 butterflies. Read all 16 points,
// barrier, compute+write, barrier.
__device__ __forceinline__ void radix8_ip(float2* __restrict__ buf,
                                          const float2* __restrict__ tw,
                                          int sLog) {
    const int i0 = threadIdx.x;          // butterfly 0
    const int i1 = threadIdx.x + NT;     // butterfly 1
    float2 a0 = buf[PADB(i0)];
    float2 a1 = buf[PADB(i0 + 1024)];
    float2 a2 = buf[PADB(i0 + 2048)];
    float2 a3 = buf[PADB(i0 + 3072)];
    float2 a4 = buf[PADB(i0 + 4096)];
    float2 a5 = buf[PADB(i0 + 5120)];
    float2 a6 = buf[PADB(i0 + 6144)];
    float2 a7 = buf[PADB(i0 + 7168)];
    float2 b0 = buf[PADB(i1)];
    float2 b1 = buf[PADB(i1 + 1024)];
    float2 b2 = buf[PADB(i1 + 2048)];
    float2 b3 = buf[PADB(i1 + 3072)];
    float2 b4 = buf[PADB(i1 + 4096)];
    float2 b5 = buf[PADB(i1 + 5120)];
    float2 b6 = buf[PADB(i1 + 6144)];
    float2 b7 = buf[PADB(i1 + 7168)];
    __syncthreads();
    bf8_compute_store(buf, tw, a0, a1, a2, a3, a4, a5, a6, a7, i0, sLog);
    bf8_compute_store(buf, tw, b0, b1, b2, b3, b4, b5, b6, b7, i1, sLog);
    __syncthreads();
}

// Final radix-2 stage (s=4096, twiddle=1): read/write sets are thread-local.
__device__ __forceinline__ void radix2_ip(float2* __restrict__ buf) {
#pragma unroll
    for (int t = 0; t < 8; t++) {
        int i = threadIdx.x + t * NT;             // 0..4095
        float2 a = buf[PADB(i)];
        float2 b = buf[PADB(i + 4096)];
        buf[PADB(i)]        = cadd(a, b);
        buf[PADB(i + 4096)] = csub(a, b);
    }
    __syncthreads();
}

// 8192-pt forward complex FFT, in place, natural order in/out.
// Caller must have a barrier between writing buf and calling this.
__device__ __forceinline__ void fft8192_ip(float2* buf, const float2* tw) {
#pragma unroll
    for (int st = 0; st < 4; st++)
        radix8_ip(buf, tw, 3 * st);               // s = 1, 8, 64, 512
    radix2_ip(buf);                               // s = 4096
}

// ============================================================================
// Filter spectra: Hhat[f][k] = rfft(h[f] padded to 16384)[k], k=0..8191,
// Nyquist packed into imag of bin 0.
// ============================================================================
__global__ void __launch_bounds__(NT, 2) hfft_kernel(const float* __restrict__ h) {
    extern __shared__ float2 sm[];
    float2* buf = sm;
    float2* tw  = sm + SBUF;
    int dIdx = blockIdx.x;
    const float2* hrow = (const float2*)(h + (size_t)dIdx * 8192);
    for (int i = threadIdx.x; i < 4096; i += NT) buf[PADB(i)] = hrow[i];
    for (int i = 4096 + threadIdx.x; i < 8192; i += NT) buf[PADB(i)] = make_float2(0.f, 0.f);
    build_tw(tw);
    __syncthreads();
    fft8192_ip(buf, tw);
    float2* out = g_Hhat + (size_t)dIdx * NC;
    float2 chalf; { float sv, cv; sincospif(-1.0f / 8192.0f, &sv, &cv); chalf = make_float2(cv, sv); }
    for (int k = threadIdx.x; k <= 4096; k += NT) {
        if (k == 0) {
            float2 Z0 = buf[PADB(0)];
            out[0] = make_float2(Z0.x + Z0.y, Z0.x - Z0.y);   // (X[0], X[Nyq])
        } else {
            int k2 = 8192 - k;
            float2 Zk  = buf[PADB(k)];
            float2 Zk2 = buf[PADB(k2)];
            float2 E  = make_float2(0.5f * (Zk.x + Zk2.x), 0.5f * (Zk.y - Zk2.y));
            float2 Dv = make_float2(Zk.x - Zk2.x, Zk.y + Zk2.y);
            float2 O  = make_float2(0.5f * Dv.y, -0.5f * Dv.x);
            float2 Wk = tw[k >> 1];                            // e^{-2pi i k/16384}
            if (k & 1) Wk = cmul(Wk, chalf);
            float2 WO = cmul(Wk, O);
            out[k] = make_float2(E.x + WO.x, E.y + WO.y);
            if (k < 4096)
                out[k2] = make_float2(E.x - WO.x, -(E.y - WO.y));
        }
    }
}

// ============================================================================
// Transposes: (B, L, D) <-> row-contiguous (B*D, L). 64(d) x 32(l) tiles,
// float2 on the D side, odd-padded smem.
// ============================================================================
#define TP 65   // padded tile row stride (floats)

__global__ void transpose_in(const float* __restrict__ u) {
    __shared__ float tile[32][TP];       // [l][d]
    int b  = blockIdx.z;
    int d0 = blockIdx.x * 64;
    int l0 = blockIdx.y * 32;
    int x = threadIdx.x, y = threadIdx.y;            // 32 x 8
    const float* ub = u + (size_t)b * L_ * D_;
#pragma unroll
    for (int j = 0; j < 4; j++) {
        int l = l0 + y + j * 8;
        float2 v = *(const float2*)(ub + (size_t)l * D_ + d0 + 2 * x);
        tile[y + j * 8][2 * x]     = v.x;
        tile[y + j * 8][2 * x + 1] = v.y;
    }
    __syncthreads();
#pragma unroll
    for (int j = 0; j < 8; j++) {
        int dd = y + j * 8;                           // 0..63
        g_uT[(size_t)(b * D_ + d0 + dd) * L_ + l0 + x] = tile[x][dd];
    }
}

__global__ void transpose_out(float* __restrict__ y_out) {
    __shared__ float tile[32][TP];       // [l][d]
    int b  = blockIdx.z;
    int d0 = blockIdx.x * 64;
    int l0 = blockIdx.y * 32;
    int x = threadIdx.x, y = threadIdx.y;
#pragma unroll
    for (int j = 0; j < 8; j++) {
        int dd = y + j * 8;
        tile[x][dd] = g_yT[(size_t)(b * D_ + d0 + dd) * L_ + l0 + x];
    }
    __syncthreads();
    float* yb = y_out + (size_t)b * L_ * D_;
#pragma unroll
    for (int j = 0; j < 4; j++) {
        int l = l0 + y + j * 8;
        float2 v = make_float2(tile[y + j * 8][2 * x], tile[y + j * 8][2 * x + 1]);
        *(float2*)(yb + (size_t)l * D_ + d0 + 2 * x) = v;
    }
}

// ============================================================================
// Per-row conv: forward FFT, fused spectral step (in-place, thread-local
// pairs), inverse FFT via conj trick, extract + contiguous store.
// ============================================================================
__global__ void __launch_bounds__(NT, 2) conv_kernel() {
    extern __shared__ float2 sm[];
    float2* buf = sm;
    float2* tw  = sm + SBUF;
    int r = blockIdx.x;              // r = b*256 + d
    int f = r >> 3;                  // filter index = (b*D + d) // B  (B=8)

    const float2* urow = (const float2*)(g_uT + (size_t)r * L_);
    for (int i = threadIdx.x; i < 4096; i += NT) buf[PADB(i)] = urow[i];
    for (int i = 4096 + threadIdx.x; i < 8192; i += NT) buf[PADB(i)] = make_float2(0.f, 0.f);
    build_tw(tw);
    __syncthreads();

    fft8192_ip(buf, tw);                     // Z in buf (barrier at end)

    const float2* Hrow = g_Hhat + (size_t)f * NC;
    float2 chalf; { float sv, cv; sincospif(-1.0f / 8192.0f, &sv, &cv); chalf = make_float2(cv, sv); }

    for (int k = threadIdx.x; k <= 4096; k += NT) {
        if (k == 0) {
            float2 Z0 = buf[PADB(0)];
            float X0 = Z0.x + Z0.y;
            float XN = Z0.x - Z0.y;
            float2 H0 = Hrow[0];
            float Y0 = X0 * H0.x;
            float YN = XN * H0.y;
            buf[PADB(0)] = make_float2(0.5f * (Y0 + YN), -0.5f * (Y0 - YN));
        } else {
            int k2 = 8192 - k;
            float2 Zk  = buf[PADB(k)];
            float2 Zk2 = buf[PADB(k2)];
            // forward rfft combine
            float2 E  = make_float2(0.5f * (Zk.x + Zk2.x), 0.5f * (Zk.y - Zk2.y));
            float2 Dv = make_float2(Zk.x - Zk2.x, Zk.y + Zk2.y);
            float2 O  = make_float2(0.5f * Dv.y, -0.5f * Dv.x);
            float2 Wk = tw[k >> 1];
            if (k & 1) Wk = cmul(Wk, chalf);
            float2 WO  = cmul(Wk, O);
            float2 Xk  = make_float2(E.x + WO.x, E.y + WO.y);
            float2 Xk2 = make_float2(E.x - WO.x, -(E.y - WO.y));
            // spectral multiply
            float2 Yk  = cmul(Xk,  Hrow[k]);
            float2 Yk2 = cmul(Xk2, Hrow[k2]);
            // irfft pre-pack with conjugation folded
            float2 Ep = make_float2(0.5f * (Yk.x + Yk2.x), 0.5f * (Yk.y - Yk2.y));
            float2 Dy = make_float2(0.5f * (Yk.x - Yk2.x), 0.5f * (Yk.y + Yk2.y));
            float2 Op = make_float2(fmaf(Wk.x, Dy.x,  Wk.y * Dy.y),
                                    fmaf(Wk.x, Dy.y, -(Wk.y * Dy.x)));
            buf[PADB(k)] = make_float2(Ep.x - Op.y, -(Ep.y + Op.x));
            if (k < 4096)
                buf[PADB(k2)] = make_float2(Ep.x + Op.y, Ep.y - Op.x);
        }
    }
    __syncthreads();

    fft8192_ip(buf, tw);                     // fft(conj(Zi)); z[n] = conj(.)/8192
    float* yrow = g_yT + (size_t)r * L_;
    const float invN = 1.0f / 8192.0f;
    for (int l = threadIdx.x; l < L_; l += NT) {
        int tpos = 4095 + l;
        float2 zr = buf[PADB(tpos >> 1)];
        yrow[l] = (tpos & 1) ? (-zr.y * invN) : (zr.x * invN);
    }
}

// ============================================================================
extern "C" void kernel_launch(void* const* d_in, const int* in_sizes, int n_in,
                              void* d_out, int out_size) {
    const float* u = (const float*)d_in[0];   // (8, 8192, 256)
    const float* h = (const float*)d_in[1];   // (256, 8192)
    float* out = (float*)d_out;               // (8, 8192, 256)

    size_t smem = (size_t)(SBUF + TWN) * sizeof(float2);  // ~86 KB
    cudaFuncSetAttribute(hfft_kernel, cudaFuncAttributeMaxDynamicSharedMemorySize, (int)smem);
    cudaFuncSetAttribute(conv_kernel, cudaFuncAttributeMaxDynamicSharedMemorySize, (int)smem);

    dim3 tb(32, 8);
    hfft_kernel<<<D_, NT, smem>>>(h);
    transpose_in<<<dim3(D_ / 64, L_ / 32, B_), tb>>>(u);
    conv_kernel<<<B_ * D_, NT, smem>>>();
    transpose_out<<<dim3(D_ / 64, L_ / 32, B_), tb>>>(out);
    (void)in_sizes; (void)n_in; (void)out_size;
}

// round 4
// speedup vs baseline: 1.9538x; 1.2402x over previous
#include <cuda_runtime.h>
#include <cstdint>

// ============================================================================
// FFTLongConv1D: y[b,l,d] = irfft( rfft(u[b,:,d],16384) * Hhat[(b*D+d)//B] )[4095+l]
// B=8, L=8192, D=256, K=8192, N=16384.
// Half-size complex FFT (8192 = 16*16*16*2), in-place Stockham radix-16 x3 +
// radix-2, boundary stages fused with gmem I/O. NT=512, 2 CTAs/SM.
// ============================================================================

#define NT 512
#define NC 8192
#define PADB(i) ((i) + ((i) >> 4))
#define SBUF 8704
#define TWN 2049
#define B_ 8
#define D_ 256
#define L_ 8192

__device__ __align__(16) float2 g_Hhat[D_ * NC];          // 16.8 MB
__device__ __align__(16) float  g_uT[B_ * D_ * L_];       // 64 MB
__device__ __align__(16) float  g_yT[B_ * D_ * L_];       // 64 MB

__device__ __forceinline__ float2 cmul(float2 a, float2 b) {
    return make_float2(fmaf(a.x, b.x, -(a.y * b.y)), fmaf(a.x, b.y, a.y * b.x));
}
__device__ __forceinline__ float2 cadd(float2 a, float2 b) { return make_float2(a.x + b.x, a.y + b.y); }
__device__ __forceinline__ float2 csub(float2 a, float2 b) { return make_float2(a.x - b.x, a.y - b.y); }

__device__ __forceinline__ void build_tw(float2* tw) {
    for (int t = threadIdx.x; t < TWN; t += NT) {
        float sv, cv;
        sincospif(-(float)t * (1.0f / 4096.0f), &sv, &cv);  // e^{-2pi i t/8192}
        tw[t] = make_float2(cv, sv);
    }
}

// In-place DFT4 (DIF): (a,b,c,d) -> (X0,X1,X2,X3)
__device__ __forceinline__ void dft4(float2& a, float2& b, float2& c, float2& d) {
    float2 apc = cadd(a, c), amc = csub(a, c);
    float2 bpd = cadd(b, d), bmd = csub(b, d);
    float2 mj  = make_float2(bmd.y, -bmd.x);   // -i*(b-d)
    a = cadd(apc, bpd);
    float2 o1 = cadd(amc, mj);
    c = csub(apc, bpd);
    d = csub(amc, mj);
    b = o1;
}

// DFT16 level 1: 4 DFT4s over strided groups {m0, m0+4, m0+8, m0+12}.
// Output S_{m0}[r] lands at x[m0 + 4r] (same positions).
__device__ __forceinline__ void l1_full(float2 x[16]) {
#pragma unroll
    for (int m0 = 0; m0 < 4; m0++)
        dft4(x[m0], x[m0 + 4], x[m0 + 8], x[m0 + 12]);
}

// Level 1 with x[8..15] == 0 (zero-padded input): DFT4(a,b,0,0).
__device__ __forceinline__ void l1_half(float2 x[16]) {
#pragma unroll
    for (int m0 = 0; m0 < 4; m0++) {
        float2 a = x[m0], b = x[m0 + 4];
        x[m0]      = cadd(a, b);
        x[m0 + 4]  = make_float2(a.x + b.y, a.y - b.x);  // a - i b
        x[m0 + 8]  = csub(a, b);
        x[m0 + 12] = make_float2(a.x - b.y, a.y + b.x);  // a + i b
    }
}

// Internal twiddles: x[m0+4r] *= w16^{r*m0}, w16 = e^{-2pi i/16}.
__device__ __forceinline__ void tw_internal(float2 x[16]) {
    const float C1 = 0.92387953251128675f;   // cos(pi/8)
    const float S1 = 0.38268343236508977f;   // sin(pi/8)
    const float C2 = 0.70710678118654752f;
    x[5]  = cmul(x[5],  make_float2(C1, -S1));                                 // w^1
    x[6]  = make_float2(C2 * (x[6].x + x[6].y),  C2 * (x[6].y - x[6].x));      // w^2
    x[7]  = cmul(x[7],  make_float2(S1, -C1));                                 // w^3
    x[9]  = make_float2(C2 * (x[9].x + x[9].y),  C2 * (x[9].y - x[9].x));      // w^2
    x[10] = make_float2(x[10].y, -x[10].x);                                    // w^4=-i
    x[11] = make_float2(-C2 * (x[11].x - x[11].y), -C2 * (x[11].x + x[11].y)); // w^6
    x[13] = cmul(x[13], make_float2(S1, -C1));                                 // w^3
    x[14] = make_float2(-C2 * (x[14].x - x[14].y), -C2 * (x[14].x + x[14].y)); // w^6
    x[15] = cmul(x[15], make_float2(-C1, S1));                                 // w^9
}

// Level 2 + outer twiddles + scattered store.
// X_{r+4t} = DFT4_t over m0 of x[m0+4r]; y_j = w^{j*ps} X_j, w = e^{-2pi i/8192}.
__device__ __forceinline__ void r16_finish(float2* __restrict__ buf,
                                           const float2* __restrict__ tw,
                                           float2 x[16], int i, int sLog) {
    const int s = 1 << sLog;
    const int ps = i & ~(s - 1);
    float2 w1  = tw[ps];
    float2 w2  = cmul(w1, w1);
    float2 w3  = cmul(w2, w1);
    float2 w4  = cmul(w2, w2);
    float2 w8  = cmul(w4, w4);
    float2 w12 = cmul(w8, w4);
    const int base = (i & (s - 1)) + ((i >> sLog) << (sLog + 4));
    // r = 0 -> j = 0,4,8,12
    dft4(x[0], x[1], x[2], x[3]);
    buf[PADB(base)]           = x[0];
    buf[PADB(base + 4 * s)]   = cmul(w4,  x[1]);
    buf[PADB(base + 8 * s)]   = cmul(w8,  x[2]);
    buf[PADB(base + 12 * s)]  = cmul(w12, x[3]);
    // r = 1 -> j = 1,5,9,13
    dft4(x[4], x[5], x[6], x[7]);
    buf[PADB(base + s)]       = cmul(w1, x[4]);
    buf[PADB(base + 5 * s)]   = cmul(cmul(w4,  w1), x[5]);
    buf[PADB(base + 9 * s)]   = cmul(cmul(w8,  w1), x[6]);
    buf[PADB(base + 13 * s)]  = cmul(cmul(w12, w1), x[7]);
    // r = 2 -> j = 2,6,10,14
    dft4(x[8], x[9], x[10], x[11]);
    buf[PADB(base + 2 * s)]   = cmul(w2, x[8]);
    buf[PADB(base + 6 * s)]   = cmul(cmul(w4,  w2), x[9]);
    buf[PADB(base + 10 * s)]  = cmul(cmul(w8,  w2), x[10]);
    buf[PADB(base + 14 * s)]  = cmul(cmul(w12, w2), x[11]);
    // r = 3 -> j = 3,7,11,15
    dft4(x[12], x[13], x[14], x[15]);
    buf[PADB(base + 3 * s)]   = cmul(w3, x[12]);
    buf[PADB(base + 7 * s)]   = cmul(cmul(w4,  w3), x[13]);
    buf[PADB(base + 11 * s)]  = cmul(cmul(w8,  w3), x[14]);
    buf[PADB(base + 15 * s)]  = cmul(cmul(w12, w3), x[15]);
}

// Generic in-place radix-16 Stockham stage.
__device__ __forceinline__ void radix16_ip(float2* buf, const float2* tw, int sLog) {
    float2 x[16];
    const int i = threadIdx.x;
#pragma unroll
    for (int m = 0; m < 16; m++) x[m] = buf[PADB(i + m * 512)];
    __syncthreads();
    l1_full(x);
    tw_internal(x);
    r16_finish(buf, tw, x, i, sLog);
    __syncthreads();
}

// Stage 1 (s=1) fused with gmem load of a zero-padded row (4096 float2 data).
// Caller must have synced after build_tw; buf must be untouched before this.
__device__ __forceinline__ void stage1_gmem(float2* buf, const float2* tw,
                                            const float2* __restrict__ row) {
    float2 x[16];
    const int i = threadIdx.x;
#pragma unroll
    for (int m = 0; m < 8; m++) x[m] = row[i + m * 512];
    l1_half(x);
    tw_internal(x);
    r16_finish(buf, tw, x, i, 0);
    __syncthreads();
}

// Forward radix-2 (s=4096): thread-local pairs {i, i+4096}, in place.
__device__ __forceinline__ void radix2_ip(float2* buf) {
#pragma unroll
    for (int t = 0; t < 8; t++) {
        int i = threadIdx.x + t * NT;
        float2 a = buf[PADB(i)], b = buf[PADB(i + 4096)];
        buf[PADB(i)]        = cadd(a, b);
        buf[PADB(i + 4096)] = csub(a, b);
    }
    __syncthreads();
}

// ============================================================================
// Filter spectra: Hhat[f][k], Nyquist packed into imag of bin 0.
// Final radix-2 fused into the combine loop (read-only smem -> gmem write).
// ============================================================================
__global__ void __launch_bounds__(NT, 2) hfft_kernel(const float* __restrict__ h) {
    extern __shared__ float2 sm[];
    float2* buf = sm;
    float2* tw  = sm + SBUF;
    int dIdx = blockIdx.x;
    build_tw(tw);
    __syncthreads();
    stage1_gmem(buf, tw, (const float2*)(h + (size_t)dIdx * 8192));
    radix16_ip(buf, tw, 4);
    radix16_ip(buf, tw, 8);

    float2* out = g_Hhat + (size_t)dIdx * NC;
    float2 chalf; { float sv, cv; sincospif(-1.0f / 8192.0f, &sv, &cv); chalf = make_float2(cv, sv); }
    for (int k = threadIdx.x; k <= 4096; k += NT) {
        if (k == 0) {
            float2 Z0 = cadd(buf[PADB(0)], buf[PADB(4096)]);
            out[0] = make_float2(Z0.x + Z0.y, Z0.x - Z0.y);   // (X[0], X[Nyq])
        } else {
            int k2 = 8192 - k;
            float2 Zk  = (k < 4096) ? cadd(buf[PADB(k)], buf[PADB(k + 4096)])
                                    : csub(buf[PADB(0)], buf[PADB(4096)]);
            float2 Zk2 = csub(buf[PADB(4096 - k)], buf[PADB(8192 - k)]);
            float2 E  = make_float2(0.5f * (Zk.x + Zk2.x), 0.5f * (Zk.y - Zk2.y));
            float2 Dv = make_float2(Zk.x - Zk2.x, Zk.y + Zk2.y);
            float2 O  = make_float2(0.5f * Dv.y, -0.5f * Dv.x);
            float2 Wk = tw[k >> 1];
            if (k & 1) Wk = cmul(Wk, chalf);
            float2 WO = cmul(Wk, O);
            out[k] = make_float2(E.x + WO.x, E.y + WO.y);
            if (k < 4096)
                out[k2] = make_float2(E.x - WO.x, -(E.y - WO.y));
        }
    }
}

// ============================================================================
// Transposes: (B, L, D) <-> row-contiguous (B*D, L)
// ============================================================================
#define TP 65

__global__ void transpose_in(const float* __restrict__ u) {
    __shared__ float tile[32][TP];
    int b  = blockIdx.z;
    int d0 = blockIdx.x * 64;
    int l0 = blockIdx.y * 32;
    int x = threadIdx.x, y = threadIdx.y;
    const float* ub = u + (size_t)b * L_ * D_;
#pragma unroll
    for (int j = 0; j < 4; j++) {
        int l = l0 + y + j * 8;
        float2 v = *(const float2*)(ub + (size_t)l * D_ + d0 + 2 * x);
        tile[y + j * 8][2 * x]     = v.x;
        tile[y + j * 8][2 * x + 1] = v.y;
    }
    __syncthreads();
#pragma unroll
    for (int j = 0; j < 8; j++) {
        int dd = y + j * 8;
        g_uT[(size_t)(b * D_ + d0 + dd) * L_ + l0 + x] = tile[x][dd];
    }
}

__global__ void transpose_out(float* __restrict__ y_out) {
    __shared__ float tile[32][TP];
    int b  = blockIdx.z;
    int d0 = blockIdx.x * 64;
    int l0 = blockIdx.y * 32;
    int x = threadIdx.x, y = threadIdx.y;
#pragma unroll
    for (int j = 0; j < 8; j++) {
        int dd = y + j * 8;
        tile[x][dd] = g_yT[(size_t)(b * D_ + d0 + dd) * L_ + l0 + x];
    }
    __syncthreads();
    float* yb = y_out + (size_t)b * L_ * D_;
#pragma unroll
    for (int j = 0; j < 4; j++) {
        int l = l0 + y + j * 8;
        float2 v = make_float2(tile[y + j * 8][2 * x], tile[y + j * 8][2 * x + 1]);
        *(float2*)(yb + (size_t)l * D_ + d0 + 2 * x) = v;
    }
}

// ============================================================================
// Per-row conv.
// ============================================================================
__global__ void __launch_bounds__(NT, 2) conv_kernel() {
    extern __shared__ float2 sm[];
    float2* buf = sm;
    float2* tw  = sm + SBUF;
    int r = blockIdx.x;              // r = b*256 + d
    int f = r >> 3;                  // filter index = (b*D+d)//B (B=8)

    build_tw(tw);
    __syncthreads();

    // Forward FFT: stage1 fused with gmem load, then s=16, s=256, radix-2.
    stage1_gmem(buf, tw, (const float2*)(g_uT + (size_t)r * L_));
    radix16_ip(buf, tw, 4);
    radix16_ip(buf, tw, 8);
    radix2_ip(buf);

    // Spectral step (in-place, thread-local pairs {k, 8192-k}).
    const float2* Hrow = g_Hhat + (size_t)f * NC;
    float2 chalf; { float sv, cv; sincospif(-1.0f / 8192.0f, &sv, &cv); chalf = make_float2(cv, sv); }
    for (int k = threadIdx.x; k <= 4096; k += NT) {
        if (k == 0) {
            float2 Z0 = buf[PADB(0)];
            float X0 = Z0.x + Z0.y;
            float XN = Z0.x - Z0.y;
            float2 H0 = Hrow[0];
            float Y0 = X0 * H0.x;
            float YN = XN * H0.y;
            buf[PADB(0)] = make_float2(0.5f * (Y0 + YN), -0.5f * (Y0 - YN));
        } else {
            int k2 = 8192 - k;
            float2 Zk  = buf[PADB(k)];
            float2 Zk2 = buf[PADB(k2)];
            float2 E  = make_float2(0.5f * (Zk.x + Zk2.x), 0.5f * (Zk.y - Zk2.y));
            float2 Dv = make_float2(Zk.x - Zk2.x, Zk.y + Zk2.y);
            float2 O  = make_float2(0.5f * Dv.y, -0.5f * Dv.x);
            float2 Wk = tw[k >> 1];
            if (k & 1) Wk = cmul(Wk, chalf);
            float2 WO  = cmul(Wk, O);
            float2 Xk  = make_float2(E.x + WO.x, E.y + WO.y);
            float2 Xk2 = make_float2(E.x - WO.x, -(E.y - WO.y));
            float2 Yk  = cmul(Xk,  Hrow[k]);
            float2 Yk2 = cmul(Xk2, Hrow[k2]);
            float2 Ep = make_float2(0.5f * (Yk.x + Yk2.x), 0.5f * (Yk.y - Yk2.y));
            float2 Dy = make_float2(0.5f * (Yk.x - Yk2.x), 0.5f * (Yk.y + Yk2.y));
            float2 Op = make_float2(fmaf(Wk.x, Dy.x,  Wk.y * Dy.y),
                                    fmaf(Wk.x, Dy.y, -(Wk.y * Dy.x)));
            buf[PADB(k)] = make_float2(Ep.x - Op.y, -(Ep.y + Op.x));
            if (k < 4096)
                buf[PADB(k2)] = make_float2(Ep.x + Op.y, Ep.y - Op.x);
        }
    }
    __syncthreads();

    // Inverse FFT (conj trick): s=1, s=16, s=256, then radix-2 fused with extract.
    radix16_ip(buf, tw, 0);
    radix16_ip(buf, tw, 4);
    radix16_ip(buf, tw, 8);

    // R[t] = radix2 output; y[l] from tpos=4095+l, t=tpos>>1 in [2047, 6143].
    float* yrow = g_yT + (size_t)r * L_;
    const float invN = 1.0f / 8192.0f;
    for (int t = 2047 + threadIdx.x; t <= 6143; t += NT) {
        float2 R;
        if (t < 4096) R = cadd(buf[PADB(t)], buf[PADB(t + 4096)]);
        else          R = csub(buf[PADB(t - 4096)], buf[PADB(t)]);
        int la = 2 * t - 4095;   // even tpos -> R.x
        int lb = la + 1;         // odd tpos  -> -R.y
        if (la >= 0) yrow[la] =  R.x * invN;
        if (lb < L_) yrow[lb] = -R.y * invN;
    }
}

// ============================================================================
extern "C" void kernel_launch(void* const* d_in, const int* in_sizes, int n_in,
                              void* d_out, int out_size) {
    const float* u = (const float*)d_in[0];   // (8, 8192, 256)
    const float* h = (const float*)d_in[1];   // (256, 8192)
    float* out = (float*)d_out;               // (8, 8192, 256)

    size_t smem = (size_t)(SBUF + TWN) * sizeof(float2);  // ~86 KB
    cudaFuncSetAttribute(hfft_kernel, cudaFuncAttributeMaxDynamicSharedMemorySize, (int)smem);
    cudaFuncSetAttribute(conv_kernel, cudaFuncAttributeMaxDynamicSharedMemorySize, (int)smem);

    dim3 tb(32, 8);
    hfft_kernel<<<D_, NT, smem>>>(h);
    transpose_in<<<dim3(D_ / 64, L_ / 32, B_), tb>>>(u);
    conv_kernel<<<B_ * D_, NT, smem>>>();
    transpose_out<<<dim3(D_ / 64, L_ / 32, B_), tb>>>(out);
    (void)in_sizes; (void)n_in; (void)out_size;
}

// round 5
// speedup vs baseline: 2.1942x; 1.1231x over previous
#include <cuda_runtime.h>
#include <cstdint>

// ============================================================================
// FFTLongConv1D: y[b,l,d] = irfft( rfft(u[b,:,d],16384) * Hhat[(b*D+d)//B] )[4095+l]
// B=8, L=8192, D=256, K=8192, N=16384.
// Half-size complex FFT (8192-pt). Conv pipeline (12 smem passes):
//   fwd:  r16(s=1, gmem-fused) r16(s=16) r16(s=256)
//   mid:  fwd-r2(s=4096) + spectral(*Hhat) + inv-r2(s=1)  -- single fused pass
//   inv:  r16(s=2) r16(s=32) r16(s=512, no twiddles, gmem-extract-fused)
// NT=512, 2 CTAs/SM (~78 KB smem each).
// ============================================================================

#define NT 512
#define NC 8192
#define PADB(i) ((i) + ((i) >> 4))
#define SBUF 8704
#define TWN_H 2049     // hfft twiddle table: e^{-2pi i t/8192}, t=0..2048
#define TWN_C 1025     // conv twiddle table: t=0..1024
#define B_ 8
#define D_ 256
#define L_ 8192

__device__ __align__(16) float2 g_Hhat[D_ * NC];          // 16.8 MB
__device__ __align__(16) float  g_uT[B_ * D_ * L_];       // 64 MB
__device__ __align__(16) float  g_yT[B_ * D_ * L_];       // 64 MB

__device__ __forceinline__ float2 cmul(float2 a, float2 b) {
    return make_float2(fmaf(a.x, b.x, -(a.y * b.y)), fmaf(a.x, b.y, a.y * b.x));
}
__device__ __forceinline__ float2 cadd(float2 a, float2 b) { return make_float2(a.x + b.x, a.y + b.y); }
__device__ __forceinline__ float2 csub(float2 a, float2 b) { return make_float2(a.x - b.x, a.y - b.y); }

__device__ __forceinline__ void build_tw(float2* tw, int n) {
    for (int t = threadIdx.x; t < n; t += NT) {
        float sv, cv;
        sincospif(-(float)t * (1.0f / 4096.0f), &sv, &cv);  // e^{-2pi i t/8192}
        tw[t] = make_float2(cv, sv);
    }
}

// In-place DFT4 (DIF): (a,b,c,d) -> (X0,X1,X2,X3)
__device__ __forceinline__ void dft4(float2& a, float2& b, float2& c, float2& d) {
    float2 apc = cadd(a, c), amc = csub(a, c);
    float2 bpd = cadd(b, d), bmd = csub(b, d);
    float2 mj  = make_float2(bmd.y, -bmd.x);   // -i*(b-d)
    a = cadd(apc, bpd);
    float2 o1 = cadd(amc, mj);
    c = csub(apc, bpd);
    d = csub(amc, mj);
    b = o1;
}

__device__ __forceinline__ void l1_full(float2 x[16]) {
#pragma unroll
    for (int m0 = 0; m0 < 4; m0++)
        dft4(x[m0], x[m0 + 4], x[m0 + 8], x[m0 + 12]);
}

// Level 1 with x[8..15] == 0 (zero-padded input): DFT4(a,b,0,0).
__device__ __forceinline__ void l1_half(float2 x[16]) {
#pragma unroll
    for (int m0 = 0; m0 < 4; m0++) {
        float2 a = x[m0], b = x[m0 + 4];
        x[m0]      = cadd(a, b);
        x[m0 + 4]  = make_float2(a.x + b.y, a.y - b.x);  // a - i b
        x[m0 + 8]  = csub(a, b);
        x[m0 + 12] = make_float2(a.x - b.y, a.y + b.x);  // a + i b
    }
}

// Internal twiddles: x[m0+4r] *= w16^{r*m0}.
__device__ __forceinline__ void tw_internal(float2 x[16]) {
    const float C1 = 0.92387953251128675f;
    const float S1 = 0.38268343236508977f;
    const float C2 = 0.70710678118654752f;
    x[5]  = cmul(x[5],  make_float2(C1, -S1));
    x[6]  = make_float2(C2 * (x[6].x + x[6].y),  C2 * (x[6].y - x[6].x));
    x[7]  = cmul(x[7],  make_float2(S1, -C1));
    x[9]  = make_float2(C2 * (x[9].x + x[9].y),  C2 * (x[9].y - x[9].x));
    x[10] = make_float2(x[10].y, -x[10].x);
    x[11] = make_float2(-C2 * (x[11].x - x[11].y), -C2 * (x[11].x + x[11].y));
    x[13] = cmul(x[13], make_float2(S1, -C1));
    x[14] = make_float2(-C2 * (x[14].x - x[14].y), -C2 * (x[14].x + x[14].y));
    x[15] = cmul(x[15], make_float2(-C1, S1));
}

// Level 2 + outer twiddles + scattered store.
__device__ __forceinline__ void r16_finish(float2* __restrict__ buf,
                                           const float2* __restrict__ tw,
                                           float2 x[16], int i, int sLog) {
    const int s = 1 << sLog;
    const int ps = i & ~(s - 1);
    float2 w1  = tw[ps];
    float2 w2  = cmul(w1, w1);
    float2 w3  = cmul(w2, w1);
    float2 w4  = cmul(w2, w2);
    float2 w8  = cmul(w4, w4);
    float2 w12 = cmul(w8, w4);
    const int base = (i & (s - 1)) + ((i >> sLog) << (sLog + 4));
    dft4(x[0], x[1], x[2], x[3]);
    buf[PADB(base)]           = x[0];
    buf[PADB(base + 4 * s)]   = cmul(w4,  x[1]);
    buf[PADB(base + 8 * s)]   = cmul(w8,  x[2]);
    buf[PADB(base + 12 * s)]  = cmul(w12, x[3]);
    dft4(x[4], x[5], x[6], x[7]);
    buf[PADB(base + s)]       = cmul(w1, x[4]);
    buf[PADB(base + 5 * s)]   = cmul(cmul(w4,  w1), x[5]);
    buf[PADB(base + 9 * s)]   = cmul(cmul(w8,  w1), x[6]);
    buf[PADB(base + 13 * s)]  = cmul(cmul(w12, w1), x[7]);
    dft4(x[8], x[9], x[10], x[11]);
    buf[PADB(base + 2 * s)]   = cmul(w2, x[8]);
    buf[PADB(base + 6 * s)]   = cmul(cmul(w4,  w2), x[9]);
    buf[PADB(base + 10 * s)]  = cmul(cmul(w8,  w2), x[10]);
    buf[PADB(base + 14 * s)]  = cmul(cmul(w12, w2), x[11]);
    dft4(x[12], x[13], x[14], x[15]);
    buf[PADB(base + 3 * s)]   = cmul(w3, x[12]);
    buf[PADB(base + 7 * s)]   = cmul(cmul(w4,  w3), x[13]);
    buf[PADB(base + 11 * s)]  = cmul(cmul(w8,  w3), x[14]);
    buf[PADB(base + 15 * s)]  = cmul(cmul(w12, w3), x[15]);
}

__device__ __forceinline__ void radix16_ip(float2* buf, const float2* tw, int sLog) {
    float2 x[16];
    const int i = threadIdx.x;
#pragma unroll
    for (int m = 0; m < 16; m++) x[m] = buf[PADB(i + m * 512)];
    __syncthreads();
    l1_full(x);
    tw_internal(x);
    r16_finish(buf, tw, x, i, sLog);
    __syncthreads();
}

// Stage 1 (s=1) fused with gmem load of a zero-padded row (4096 float2 data).
__device__ __forceinline__ void stage1_gmem(float2* buf, const float2* tw,
                                            const float2* __restrict__ row) {
    float2 x[16];
    const int i = threadIdx.x;
#pragma unroll
    for (int m = 0; m < 8; m++) x[m] = row[i + m * 512];
    l1_half(x);
    tw_internal(x);
    r16_finish(buf, tw, x, i, 0);
    __syncthreads();
}

// Spectral step for packed conjugate pair (ka, 8192-ka).
// Zk = Z[ka], Zk2 = Z[8192-ka], Wk = e^{-2pi i ka/16384}. Outputs Zc (conjugated
// irfft pre-pack) at positions ka (Zca) and 8192-ka (Zcb).
__device__ __forceinline__ void spectral_pair(float2 Zk, float2 Zk2, float2 Wk,
                                              float2 Hk, float2 Hk2,
                                              float2& Zca, float2& Zcb) {
    float2 E  = make_float2(0.5f * (Zk.x + Zk2.x), 0.5f * (Zk.y - Zk2.y));
    float2 Dv = make_float2(Zk.x - Zk2.x, Zk.y + Zk2.y);
    float2 O  = make_float2(0.5f * Dv.y, -0.5f * Dv.x);
    float2 WO = cmul(Wk, O);
    float2 Xk  = make_float2(E.x + WO.x, E.y + WO.y);
    float2 Xk2 = make_float2(E.x - WO.x, -(E.y - WO.y));
    float2 Yk  = cmul(Xk,  Hk);
    float2 Yk2 = cmul(Xk2, Hk2);
    float2 Ep = make_float2(0.5f * (Yk.x + Yk2.x), 0.5f * (Yk.y - Yk2.y));
    float2 Dy = make_float2(0.5f * (Yk.x - Yk2.x), 0.5f * (Yk.y + Yk2.y));
    float2 Op = make_float2(fmaf(Wk.x, Dy.x,  Wk.y * Dy.y),
                            fmaf(Wk.x, Dy.y, -(Wk.y * Dy.x)));
    Zca = make_float2(Ep.x - Op.y, -(Ep.y + Op.x));
    Zcb = make_float2(Ep.x + Op.y, Ep.y - Op.x);
}

// Fused middle pass: forward radix-2 (s=4096) + spectral multiply + inverse
// radix-2 (s=1, twiddle w^m = Wk^2). One smem R + one smem W.
__device__ __forceinline__ void mid_fused(float2* buf, const float2* __restrict__ tw,
                                          const float2* __restrict__ Hrow) {
    const int tid = threadIdx.x;
    float2 A[4], Bv[4], C[4], Dd[4];
#pragma unroll
    for (int it = 0; it < 4; it++) {
        int k = tid + it * NT;
        int ka = k, kb = k + 4096, kc = 4096 - k, kd = 8192 - k;
        if (k == 0) { kc = 2048; kd = 6144; }
        A[it]  = buf[PADB(ka)];
        Bv[it] = buf[PADB(kb)];
        C[it]  = buf[PADB(kc)];
        Dd[it] = buf[PADB(kd)];
    }
    __syncthreads();
    float2 chalf; { float sv, cv; sincospif(-1.0f / 8192.0f, &sv, &cv); chalf = make_float2(cv, sv); }
#pragma unroll
    for (int it = 0; it < 4; it++) {
        int k = tid + it * NT;
        if (k == 0) {
            // m=0: bins 0 (DC+Nyq packed) and 4096 (self-conjugate)
            float2 Z0 = cadd(A[0], Bv[0]);
            float2 Z4 = csub(A[0], Bv[0]);
            float2 H0 = Hrow[0];
            float X0 = Z0.x + Z0.y, XN = Z0.x - Z0.y;
            float Y0 = X0 * H0.x,   YN = XN * H0.y;
            float2 Zc0 = make_float2(0.5f * (Y0 + YN), -0.5f * (Y0 - YN));
            float2 Zc4a, Zc4b;
            spectral_pair(Z4, Z4, make_float2(0.f, -1.f), Hrow[4096], Hrow[4096], Zc4a, Zc4b);
            buf[PADB(0)] = cadd(Zc0, Zc4a);
            buf[PADB(1)] = csub(Zc0, Zc4a);
            // m=2048: pair (2048, 6144), inv-r2 twiddle w^2048 = -i
            float2 Z2 = cadd(C[0], Dd[0]);
            float2 Z6 = csub(C[0], Dd[0]);
            const float rh = 0.70710678118654752f;
            float2 Zca, Zcb;
            spectral_pair(Z2, Z6, make_float2(rh, -rh), Hrow[2048], Hrow[6144], Zca, Zcb);
            float2 d = csub(Zca, Zcb);
            buf[PADB(4096)] = cadd(Zca, Zcb);
            buf[PADB(4097)] = make_float2(d.y, -d.x);
        } else {
            float2 Zk  = cadd(A[it], Bv[it]);    // Z[k]
            float2 Zp  = csub(A[it], Bv[it]);    // Z[4096+k]
            float2 Zm  = cadd(C[it], Dd[it]);    // Z[4096-k]
            float2 Zk2 = csub(C[it], Dd[it]);    // Z[8192-k]
            float2 Wk = tw[k >> 1];
            if (k & 1) Wk = cmul(Wk, chalf);     // e^{-2pi i k/16384}
            float2 Zca, Zcb, Zcc, Zcd;
            spectral_pair(Zk, Zk2, Wk, Hrow[k], Hrow[8192 - k], Zca, Zcb);
            float2 Wm = make_float2(-Wk.y, -Wk.x);  // e^{-2pi i (4096-k)/16384}
            spectral_pair(Zm, Zp, Wm, Hrow[4096 - k], Hrow[4096 + k], Zcc, Zcd);
            // inverse radix-2, s=1: pair m=k uses Zc[k],Zc[k+4096]; tw v=Wk^2
            float2 v  = cmul(Wk, Wk);
            float2 d1 = csub(Zca, Zcd);
            buf[PADB(2 * k)]     = cadd(Zca, Zcd);
            buf[PADB(2 * k + 1)] = cmul(v, d1);
            // pair m=4096-k uses Zc[4096-k],Zc[8192-k]; tw -conj(v)
            float2 vp = make_float2(-v.x, v.y);
            float2 d2 = csub(Zcc, Zcb);
            buf[PADB(8192 - 2 * k)] = cadd(Zcc, Zcb);
            buf[PADB(8193 - 2 * k)] = cmul(vp, d2);
        }
    }
    __syncthreads();
}

// Last inverse stage (s=512, ps=0 -> no outer twiddles) fused with extraction:
// R[i+512j]; y_full[2t]=R[t].x/8192, y_full[2t+1]=-R[t].y/8192; y[l]=y_full[4095+l].
__device__ __forceinline__ void last16_extract(const float2* __restrict__ buf,
                                               float* __restrict__ yrow) {
    float2 x[16];
    const int i = threadIdx.x;
#pragma unroll
    for (int m = 0; m < 16; m++) x[m] = buf[PADB(i + m * 512)];
    l1_full(x);
    tw_internal(x);
    const float invN = 1.0f / 8192.0f;
#pragma unroll
    for (int r = 0; r < 4; r++) {
        dft4(x[4 * r], x[4 * r + 1], x[4 * r + 2], x[4 * r + 3]);
#pragma unroll
        for (int t = 0; t < 4; t++) {
            int j = r + 4 * t;                 // output index: R[i + 512*j]
            int tp = i + 512 * j;
            if (tp >= 2047 && tp <= 6143) {
                float2 R = x[4 * r + t];
                int la = 2 * tp - 4095;
                if (la >= 0)     yrow[la]     =  R.x * invN;
                if (la + 1 < L_) yrow[la + 1] = -R.y * invN;
            }
        }
    }
}

// ============================================================================
// Filter spectra: Hhat[f][k], Nyquist packed into imag of bin 0.
// ============================================================================
__global__ void __launch_bounds__(NT, 2) hfft_kernel(const float* __restrict__ h) {
    extern __shared__ float2 sm[];
    float2* buf = sm;
    float2* tw  = sm + SBUF;
    int dIdx = blockIdx.x;
    build_tw(tw, TWN_H);
    __syncthreads();
    stage1_gmem(buf, tw, (const float2*)(h + (size_t)dIdx * 8192));
    radix16_ip(buf, tw, 4);
    radix16_ip(buf, tw, 8);

    float2* out = g_Hhat + (size_t)dIdx * NC;
    float2 chalf; { float sv, cv; sincospif(-1.0f / 8192.0f, &sv, &cv); chalf = make_float2(cv, sv); }
    for (int k = threadIdx.x; k <= 4096; k += NT) {
        if (k == 0) {
            float2 Z0 = cadd(buf[PADB(0)], buf[PADB(4096)]);
            out[0] = make_float2(Z0.x + Z0.y, Z0.x - Z0.y);
        } else {
            int k2 = 8192 - k;
            float2 Zk  = (k < 4096) ? cadd(buf[PADB(k)], buf[PADB(k + 4096)])
                                    : csub(buf[PADB(0)], buf[PADB(4096)]);
            float2 Zk2 = csub(buf[PADB(4096 - k)], buf[PADB(8192 - k)]);
            float2 E  = make_float2(0.5f * (Zk.x + Zk2.x), 0.5f * (Zk.y - Zk2.y));
            float2 Dv = make_float2(Zk.x - Zk2.x, Zk.y + Zk2.y);
            float2 O  = make_float2(0.5f * Dv.y, -0.5f * Dv.x);
            float2 Wk = tw[k >> 1];
            if (k & 1) Wk = cmul(Wk, chalf);
            float2 WO = cmul(Wk, O);
            out[k] = make_float2(E.x + WO.x, E.y + WO.y);
            if (k < 4096)
                out[k2] = make_float2(E.x - WO.x, -(E.y - WO.y));
        }
    }
}

// ============================================================================
// Transposes: (B, L, D) <-> row-contiguous (B*D, L)
// ============================================================================
#define TP 65

__global__ void transpose_in(const float* __restrict__ u) {
    __shared__ float tile[32][TP];
    int b  = blockIdx.z;
    int d0 = blockIdx.x * 64;
    int l0 = blockIdx.y * 32;
    int x = threadIdx.x, y = threadIdx.y;
    const float* ub = u + (size_t)b * L_ * D_;
#pragma unroll
    for (int j = 0; j < 4; j++) {
        int l = l0 + y + j * 8;
        float2 v = *(const float2*)(ub + (size_t)l * D_ + d0 + 2 * x);
        tile[y + j * 8][2 * x]     = v.x;
        tile[y + j * 8][2 * x + 1] = v.y;
    }
    __syncthreads();
#pragma unroll
    for (int j = 0; j < 8; j++) {
        int dd = y + j * 8;
        g_uT[(size_t)(b * D_ + d0 + dd) * L_ + l0 + x] = tile[x][dd];
    }
}

__global__ void transpose_out(float* __restrict__ y_out) {
    __shared__ float tile[32][TP];
    int b  = blockIdx.z;
    int d0 = blockIdx.x * 64;
    int l0 = blockIdx.y * 32;
    int x = threadIdx.x, y = threadIdx.y;
#pragma unroll
    for (int j = 0; j < 8; j++) {
        int dd = y + j * 8;
        tile[x][dd] = g_yT[(size_t)(b * D_ + d0 + dd) * L_ + l0 + x];
    }
    __syncthreads();
    float* yb = y_out + (size_t)b * L_ * D_;
#pragma unroll
    for (int j = 0; j < 4; j++) {
        int l = l0 + y + j * 8;
        float2 v = make_float2(tile[y + j * 8][2 * x], tile[y + j * 8][2 * x + 1]);
        *(float2*)(yb + (size_t)l * D_ + d0 + 2 * x) = v;
    }
}

// ============================================================================
// Per-row conv: 12 smem passes total.
// ============================================================================
__global__ void __launch_bounds__(NT, 2) conv_kernel() {
    extern __shared__ float2 sm[];
    float2* buf = sm;
    float2* tw  = sm + SBUF;        // TWN_C entries
    int r = blockIdx.x;             // r = b*256 + d
    int f = r >> 3;                 // filter index = (b*D+d)//B  (B=8)

    build_tw(tw, TWN_C);
    __syncthreads();

    // forward: s=1 (gmem-fused), s=16, s=256
    stage1_gmem(buf, tw, (const float2*)(g_uT + (size_t)r * L_));
    radix16_ip(buf, tw, 4);
    radix16_ip(buf, tw, 8);

    // fused: fwd-r2 + spectral + inv-r2
    mid_fused(buf, tw, g_Hhat + (size_t)f * NC);

    // inverse: s=2, s=32, then s=512 fused with extraction
    radix16_ip(buf, tw, 1);
    radix16_ip(buf, tw, 5);
    last16_extract(buf, g_yT + (size_t)r * L_);
}

// ============================================================================
extern "C" void kernel_launch(void* const* d_in, const int* in_sizes, int n_in,
                              void* d_out, int out_size) {
    const float* u = (const float*)d_in[0];   // (8, 8192, 256)
    const float* h = (const float*)d_in[1];   // (256, 8192)
    float* out = (float*)d_out;               // (8, 8192, 256)

    size_t smem_h = (size_t)(SBUF + TWN_H) * sizeof(float2);  // ~86 KB
    size_t smem_c = (size_t)(SBUF + TWN_C) * sizeof(float2);  // ~78 KB
    cudaFuncSetAttribute(hfft_kernel, cudaFuncAttributeMaxDynamicSharedMemorySize, (int)smem_h);
    cudaFuncSetAttribute(conv_kernel, cudaFuncAttributeMaxDynamicSharedMemorySize, (int)smem_c);

    dim3 tb(32, 8);
    hfft_kernel<<<D_, NT, smem_h>>>(h);
    transpose_in<<<dim3(D_ / 64, L_ / 32, B_), tb>>>(u);
    conv_kernel<<<B_ * D_, NT, smem_c>>>();
    transpose_out<<<dim3(D_ / 64, L_ / 32, B_), tb>>>(out);
    (void)in_sizes; (void)n_in; (void)out_size;
}